// round 7
// baseline (speedup 1.0000x reference)
#include <cuda_runtime.h>
#include <cstdint>

#define B_SZ 2048
#define T_SZ 256
#define IN_SZ 65
#define H_SZ 64
#define G_SZ 256           // 4*H
#define BR 16              // batch rows per block
#define NP 8               // row pairs per block
#define PST 10             // ull stride per k-row (80B, keeps 16B alignment)
#define NTH 512

typedef unsigned long long ull;

__device__ __forceinline__ ull ffma2(ull a, ull b, ull c) {
    ull d;
    asm("fma.rn.f32x2 %0, %1, %2, %3;" : "=l"(d) : "l"(a), "l"(b), "l"(c));
    return d;
}
__device__ __forceinline__ ull fadd2(ull a, ull b) {
    ull d;
    asm("add.rn.f32x2 %0, %1, %2;" : "=l"(d) : "l"(a), "l"(b));
    return d;
}
__device__ __forceinline__ ull fdup(float v) {
    ull d;
    asm("mov.b64 %0, {%1, %1};" : "=l"(d) : "f"(v));
    return d;
}
__device__ __forceinline__ ull fpack(float lo, float hi) {
    ull d;
    asm("mov.b64 %0, {%1, %2};" : "=l"(d) : "f"(lo), "f"(hi));
    return d;
}
__device__ __forceinline__ void funpack(ull v, float& lo, float& hi) {
    asm("mov.b64 {%0, %1}, %2;" : "=f"(lo), "=f"(hi) : "l"(v));
}
__device__ __forceinline__ float ex2f(float x) {
    float y; asm("ex2.approx.f32 %0, %1;" : "=f"(y) : "f"(x)); return y;
}
__device__ __forceinline__ float rcpf(float x) {
    float y; asm("rcp.approx.f32 %0, %1;" : "=f"(y) : "f"(x)); return y;
}
__device__ __forceinline__ float sigf(float x) {
    return rcpf(1.0f + ex2f(-1.4426950408889634f * x));
}
__device__ __forceinline__ float tanhf_(float x) {
    return fmaf(2.0f, rcpf(1.0f + ex2f(-2.8853900817779268f * x)), -1.0f);
}

// dynamic smem layout (bytes)
#define XS_BYTES (IN_SZ * PST * 8)            // 5200   x row-pairs [65][PST]
#define HS_BYTES (H_SZ * PST * 8)             // 5120   h row-pairs [64][PST]
#define XG_BYTES (2 * NP * G_SZ * 8)          // 32768  x-part gates, ping-pong [2][8][256]
#define HG_BYTES (NP * G_SZ * 8)              // 16384  h-part gates [8][256]
#define SMEM_TOTAL (XS_BYTES + HS_BYTES + XG_BYTES + HG_BYTES)  // 59472

// x-projection MAC: 65 k, 8 row-pairs, gate j; dst[p*G_SZ] += layout
__device__ __forceinline__ void xmac_run(const ull* __restrict__ xsbuf,
                                         const float* __restrict__ w_,
                                         ull* __restrict__ dst) {
    ull a0 = 0, a1 = 0, a2 = 0, a3 = 0, a4 = 0, a5 = 0, a6 = 0, a7 = 0;
    const ull* sp = xsbuf;
#pragma unroll
    for (int k = 0; k < IN_SZ; ++k) {
        const ull wd = fdup(w_[k]);
        ulonglong2 p01 = *(const ulonglong2*)(sp);
        ulonglong2 p23 = *(const ulonglong2*)(sp + 2);
        ulonglong2 p45 = *(const ulonglong2*)(sp + 4);
        ulonglong2 p67 = *(const ulonglong2*)(sp + 6);
        sp += PST;
        a0 = ffma2(wd, p01.x, a0); a1 = ffma2(wd, p01.y, a1);
        a2 = ffma2(wd, p23.x, a2); a3 = ffma2(wd, p23.y, a3);
        a4 = ffma2(wd, p45.x, a4); a5 = ffma2(wd, p45.y, a5);
        a6 = ffma2(wd, p67.x, a6); a7 = ffma2(wd, p67.y, a7);
    }
    dst[0 * G_SZ] = a0; dst[1 * G_SZ] = a1;
    dst[2 * G_SZ] = a2; dst[3 * G_SZ] = a3;
    dst[4 * G_SZ] = a4; dst[5 * G_SZ] = a5;
    dst[6 * G_SZ] = a6; dst[7 * G_SZ] = a7;
}

__global__ __launch_bounds__(NTH, 1)
void lstm_fused_kernel(const float* __restrict__ x,
                       const float* __restrict__ Wih,
                       const float* __restrict__ Whh,
                       const float* __restrict__ bih,
                       const float* __restrict__ bhh,
                       const float* __restrict__ fcW,
                       const float* __restrict__ fcb,
                       float* __restrict__ out) {
    extern __shared__ char sm_raw[];
    ull* xsbuf = (ull*)sm_raw;                                   // [65][PST]
    ull* hsbuf = (ull*)(sm_raw + XS_BYTES);                      // [64][PST]
    ull* xg    = (ull*)(sm_raw + XS_BYTES + HS_BYTES);           // [2][8][256]
    ull* hg    = (ull*)(sm_raw + XS_BYTES + HS_BYTES + XG_BYTES);// [8][256]

    const int tid = threadIdx.x;
    const int b0  = blockIdx.x * BR;
    const bool isX = tid >= 256;       // warps 8-15: x-engine; warps 0-7: h-engine + update
    const int j = tid & 255;           // owned gate column

    // ---- weights -> registers (one-time) ----
    float w_[IN_SZ];
    if (isX) {
#pragma unroll
        for (int k = 0; k < IN_SZ; ++k) w_[k] = Wih[j * IN_SZ + k];
    } else {
#pragma unroll
        for (int k = 0; k < H_SZ; ++k) w_[k] = Whh[j * H_SZ + k];
        w_[H_SZ] = 0.0f;
    }

    // ---- init: zero hsbuf, fill xsbuf with x(t=0) ----
    for (int i = tid; i < H_SZ * PST; i += NTH) hsbuf[i] = 0ULL;
    for (int idx = tid; idx < 520; idx += NTH) {
        const int p = idx / 65, k = idx - p * 65;
        const float* xp = x + (size_t)(b0 + 2 * p) * T_SZ * IN_SZ + k;
        xsbuf[k * PST + p] = fpack(xp[0], xp[(size_t)T_SZ * IN_SZ]);
    }

    // ---- update mapping (tid < 256): unit uu, row-pairs up0 and up0+4 ----
    const int up0 = tid >> 6;          // 0..3
    const int uu  = tid & 63;          // 0..63
    float bI = 0.f, bF = 0.f, bG = 0.f, bO = 0.f;
    if (!isX) {
        bI = bih[uu]       + bhh[uu];
        bF = bih[64 + uu]  + bhh[64 + uu];
        bG = bih[128 + uu] + bhh[128 + uu];
        bO = bih[192 + uu] + bhh[192 + uu];
    }
    float c0L = 0.0f, c0H = 0.0f, c1L = 0.0f, c1H = 0.0f;

    __syncthreads();

    // ---- prologue: x-MAC(0) -> xg[0] ----
    if (isX) xmac_run(xsbuf, w_, xg + j);
    __syncthreads();

    for (int t = 0; t < T_SZ; ++t) {
        const bool hasNext = (t + 1 < T_SZ);

        // ===== phase A =====
        if (!isX) {
            // h-MAC(t): 64 k over hsbuf (h[t-1])
            ull a0 = 0, a1 = 0, a2 = 0, a3 = 0, a4 = 0, a5 = 0, a6 = 0, a7 = 0;
            const ull* sp = hsbuf;
#pragma unroll
            for (int k = 0; k < H_SZ; ++k) {
                const ull wd = fdup(w_[k]);
                ulonglong2 p01 = *(const ulonglong2*)(sp);
                ulonglong2 p23 = *(const ulonglong2*)(sp + 2);
                ulonglong2 p45 = *(const ulonglong2*)(sp + 4);
                ulonglong2 p67 = *(const ulonglong2*)(sp + 6);
                sp += PST;
                a0 = ffma2(wd, p01.x, a0); a1 = ffma2(wd, p01.y, a1);
                a2 = ffma2(wd, p23.x, a2); a3 = ffma2(wd, p23.y, a3);
                a4 = ffma2(wd, p45.x, a4); a5 = ffma2(wd, p45.y, a5);
                a6 = ffma2(wd, p67.x, a6); a7 = ffma2(wd, p67.y, a7);
            }
            ull* g = hg + j;
            g[0 * G_SZ] = a0; g[1 * G_SZ] = a1;
            g[2 * G_SZ] = a2; g[3 * G_SZ] = a3;
            g[4 * G_SZ] = a4; g[5 * G_SZ] = a5;
            g[6 * G_SZ] = a6; g[7 * G_SZ] = a7;
        } else if (hasNext) {
            // load x(t+1) -> xsbuf (latency covered by H-group's MAC)
            const int i0 = tid - 256;
#pragma unroll
            for (int m = 0; m < 3; ++m) {
                const int idx = i0 + m * 256;
                if (m < 2 || idx < 520) {
                    const int p = idx / 65, k = idx - p * 65;
                    const float* xp = x + ((size_t)(b0 + 2 * p) * T_SZ + (t + 1)) * IN_SZ + k;
                    xsbuf[k * PST + p] = fpack(xp[0], xp[(size_t)T_SZ * IN_SZ]);
                }
            }
        }
        __syncthreads();

        // ===== phase B =====
        if (!isX) {
            // update(t): gates = xg[t&1] + hg + bias
            const ull* xgc = xg + (t & 1) * (NP * G_SZ);
#pragma unroll
            for (int half = 0; half < 2; ++half) {
                const int up = up0 + half * 4;
                float& cL = half ? c1L : c0L;
                float& cH = half ? c1H : c0H;
                const ull* gx = xgc + up * G_SZ;
                const ull* gh = hg + up * G_SZ;
                ull sI = fadd2(gx[uu],       gh[uu]);
                ull sF = fadd2(gx[64 + uu],  gh[64 + uu]);
                ull sG = fadd2(gx[128 + uu], gh[128 + uu]);
                ull sO = fadd2(gx[192 + uu], gh[192 + uu]);
                float iL, iH, fL, fH, gL, gH, oL, oH;
                funpack(sI, iL, iH); funpack(sF, fL, fH);
                funpack(sG, gL, gH); funpack(sO, oL, oH);

                float iv = sigf(iL + bI);
                float fv = sigf(fL + bF);
                float gv = tanhf_(gL + bG);
                float ov = sigf(oL + bO);
                cL = fv * cL + iv * gv;
                float hLo = ov * tanhf_(cL);

                iv = sigf(iH + bI);
                fv = sigf(fH + bF);
                gv = tanhf_(gH + bG);
                ov = sigf(oH + bO);
                cH = fv * cH + iv * gv;
                float hHi = ov * tanhf_(cH);

                hsbuf[uu * PST + up] = fpack(hLo, hHi);
            }
        } else if (hasNext) {
            // x-MAC(t+1) -> xg[(t+1)&1] (overlaps update's MUFU chain)
            xmac_run(xsbuf, w_, xg + ((t + 1) & 1) * (NP * G_SZ) + j);
        }
        __syncthreads();
    }

    // ---- final FC head: out[b][o] = sigmoid(h . fcW[o] + fcb[o]) ----
    if (tid < BR * 7) {
        int r = tid / 7;
        int o = tid - r * 7;
        float s = fcb[o];
        const float* wrow = fcW + o * H_SZ;
#pragma unroll 8
        for (int u = 0; u < H_SZ; ++u) {
            float lo, hi;
            funpack(hsbuf[u * PST + (r >> 1)], lo, hi);
            s += wrow[u] * ((r & 1) ? hi : lo);
        }
        out[(size_t)(b0 + r) * 7 + o] = sigf(s);
    }
}

extern "C" void kernel_launch(void* const* d_in, const int* in_sizes, int n_in,
                              void* d_out, int out_size) {
    const float* x    = (const float*)d_in[0];
    const float* Wih  = (const float*)d_in[1];
    const float* Whh  = (const float*)d_in[2];
    const float* bih  = (const float*)d_in[3];
    const float* bhh  = (const float*)d_in[4];
    const float* fcW  = (const float*)d_in[5];
    const float* fcb  = (const float*)d_in[6];
    float* out = (float*)d_out;

    cudaFuncSetAttribute(lstm_fused_kernel,
                         cudaFuncAttributeMaxDynamicSharedMemorySize, SMEM_TOTAL);
    lstm_fused_kernel<<<B_SZ / BR, NTH, SMEM_TOTAL>>>(x, Wih, Whh, bih, bhh, fcW, fcb, out);
}

// round 8
// speedup vs baseline: 1.0639x; 1.0639x over previous
#include <cuda_runtime.h>
#include <cstdint>

#define B_SZ 2048
#define T_SZ 256
#define IN_SZ 65
#define H_SZ 64
#define G_SZ 256           // 4*H
#define BR 16              // batch rows per block
#define NP 8               // row pairs per block
#define PST 10             // ull stride per k-row (80B, keeps 16B alignment)
#define NTH 256

typedef unsigned long long ull;

__device__ __forceinline__ ull ffma2(ull a, ull b, ull c) {
    ull d;
    asm("fma.rn.f32x2 %0, %1, %2, %3;" : "=l"(d) : "l"(a), "l"(b), "l"(c));
    return d;
}
__device__ __forceinline__ ull fadd2(ull a, ull b) {
    ull d;
    asm("add.rn.f32x2 %0, %1, %2;" : "=l"(d) : "l"(a), "l"(b));
    return d;
}
__device__ __forceinline__ ull fdup(float v) {
    ull d;
    asm("mov.b64 %0, {%1, %1};" : "=l"(d) : "f"(v));
    return d;
}
__device__ __forceinline__ ull fpack(float lo, float hi) {
    ull d;
    asm("mov.b64 %0, {%1, %2};" : "=l"(d) : "f"(lo), "f"(hi));
    return d;
}
__device__ __forceinline__ void funpack(ull v, float& lo, float& hi) {
    asm("mov.b64 {%0, %1}, %2;" : "=f"(lo), "=f"(hi) : "l"(v));
}
__device__ __forceinline__ float ex2f(float x) {
    float y; asm("ex2.approx.f32 %0, %1;" : "=f"(y) : "f"(x)); return y;
}
__device__ __forceinline__ float rcpf(float x) {
    float y; asm("rcp.approx.f32 %0, %1;" : "=f"(y) : "f"(x)); return y;
}
__device__ __forceinline__ float sigf(float x) {
    return rcpf(1.0f + ex2f(-1.4426950408889634f * x));
}
__device__ __forceinline__ float tanhf_(float x) {
    return fmaf(2.0f, rcpf(1.0f + ex2f(-2.8853900817779268f * x)), -1.0f);
}

// dynamic smem layout (bytes)
#define XS_BYTES (IN_SZ * PST * 8)            // 5200   x row-pairs [65][PST]
#define HS_BYTES (H_SZ * PST * 8)             // 5120   h row-pairs [64][PST]
#define XG_BYTES (2 * NP * G_SZ * 8)          // 32768  x-part gates, ping-pong [2][8][256]
#define HG_BYTES (NP * G_SZ * 8)              // 16384  h-part gates [8][256]
#define SMEM_TOTAL (XS_BYTES + HS_BYTES + XG_BYTES + HG_BYTES)  // 59472

// MAC over N k-rows for TWO gate columns (j0, j0+128), 8 row-pairs.
template<int N>
__device__ __forceinline__ void mac2(const ull* __restrict__ sp,
                                     const float* __restrict__ w0_,
                                     const float* __restrict__ w1_,
                                     ull* __restrict__ g /* gbuf + j0 */) {
    ull a0 = 0, a1 = 0, a2 = 0, a3 = 0, a4 = 0, a5 = 0, a6 = 0, a7 = 0;
    ull b0 = 0, b1 = 0, b2 = 0, b3 = 0, b4 = 0, b5 = 0, b6 = 0, b7 = 0;
#pragma unroll
    for (int k = 0; k < N; ++k) {
        const ull wd0 = fdup(w0_[k]);
        const ull wd1 = fdup(w1_[k]);
        ulonglong2 p01 = *(const ulonglong2*)(sp);
        ulonglong2 p23 = *(const ulonglong2*)(sp + 2);
        ulonglong2 p45 = *(const ulonglong2*)(sp + 4);
        ulonglong2 p67 = *(const ulonglong2*)(sp + 6);
        sp += PST;
        a0 = ffma2(wd0, p01.x, a0); a1 = ffma2(wd0, p01.y, a1);
        a2 = ffma2(wd0, p23.x, a2); a3 = ffma2(wd0, p23.y, a3);
        a4 = ffma2(wd0, p45.x, a4); a5 = ffma2(wd0, p45.y, a5);
        a6 = ffma2(wd0, p67.x, a6); a7 = ffma2(wd0, p67.y, a7);
        b0 = ffma2(wd1, p01.x, b0); b1 = ffma2(wd1, p01.y, b1);
        b2 = ffma2(wd1, p23.x, b2); b3 = ffma2(wd1, p23.y, b3);
        b4 = ffma2(wd1, p45.x, b4); b5 = ffma2(wd1, p45.y, b5);
        b6 = ffma2(wd1, p67.x, b6); b7 = ffma2(wd1, p67.y, b7);
    }
    g[0 * G_SZ] = a0; g[1 * G_SZ] = a1;
    g[2 * G_SZ] = a2; g[3 * G_SZ] = a3;
    g[4 * G_SZ] = a4; g[5 * G_SZ] = a5;
    g[6 * G_SZ] = a6; g[7 * G_SZ] = a7;
    ull* g2 = g + 128;
    g2[0 * G_SZ] = b0; g2[1 * G_SZ] = b1;
    g2[2 * G_SZ] = b2; g2[3 * G_SZ] = b3;
    g2[4 * G_SZ] = b4; g2[5 * G_SZ] = b5;
    g2[6 * G_SZ] = b6; g2[7 * G_SZ] = b7;
}

__global__ __launch_bounds__(NTH, 1)
void lstm_fused_kernel(const float* __restrict__ x,
                       const float* __restrict__ Wih,
                       const float* __restrict__ Whh,
                       const float* __restrict__ bih,
                       const float* __restrict__ bhh,
                       const float* __restrict__ fcW,
                       const float* __restrict__ fcb,
                       float* __restrict__ out) {
    extern __shared__ char sm_raw[];
    ull* xsbuf = (ull*)sm_raw;                                    // [65][PST]
    ull* hsbuf = (ull*)(sm_raw + XS_BYTES);                       // [64][PST]
    ull* xg    = (ull*)(sm_raw + XS_BYTES + HS_BYTES);            // [2][8][256]
    ull* hg    = (ull*)(sm_raw + XS_BYTES + HS_BYTES + XG_BYTES); // [8][256]

    const int tid = threadIdx.x;
    const int b0  = blockIdx.x * BR;
    const bool isH = tid < 128;        // warps 0-3: h-MAC + update; warps 4-7: x-engine
    const int j0 = tid & 127;          // owned gate columns j0 and j0+128

    // ---- weights -> registers (one-time) ----
    float w0_[IN_SZ], w1_[IN_SZ];
    if (isH) {
#pragma unroll
        for (int k = 0; k < H_SZ; ++k) {
            w0_[k] = Whh[j0 * H_SZ + k];
            w1_[k] = Whh[(j0 + 128) * H_SZ + k];
        }
        w0_[H_SZ] = 0.0f; w1_[H_SZ] = 0.0f;
    } else {
#pragma unroll
        for (int k = 0; k < IN_SZ; ++k) {
            w0_[k] = Wih[j0 * IN_SZ + k];
            w1_[k] = Wih[(j0 + 128) * IN_SZ + k];
        }
    }

    // ---- init: zero hsbuf, fill xsbuf with x(t=0) ----
    for (int i = tid; i < H_SZ * PST; i += NTH) hsbuf[i] = 0ULL;
    for (int idx = tid; idx < 520; idx += NTH) {
        const int p = idx / 65, k = idx - p * 65;
        const float* xp = x + (size_t)(b0 + 2 * p) * T_SZ * IN_SZ + k;
        xsbuf[k * PST + p] = fpack(xp[0], xp[(size_t)T_SZ * IN_SZ]);
    }

    // ---- update mapping (H threads): unit uu, row-pairs pg*4 .. pg*4+3 ----
    const int uu = tid & 63;           // 0..63
    const int pg = (tid >> 6) & 1;     // 0..1
    float bI = 0.f, bF = 0.f, bG = 0.f, bO = 0.f;
    if (isH) {
        bI = bih[uu]       + bhh[uu];
        bF = bih[64 + uu]  + bhh[64 + uu];
        bG = bih[128 + uu] + bhh[128 + uu];
        bO = bih[192 + uu] + bhh[192 + uu];
    }
    float cL[4] = {0.f, 0.f, 0.f, 0.f};
    float cH[4] = {0.f, 0.f, 0.f, 0.f};

    __syncthreads();

    // ---- prologue: x-MAC(0) -> xg[0] ----
    if (!isH) mac2<IN_SZ>(xsbuf, w0_, w1_, xg + j0);
    __syncthreads();

    for (int t = 0; t < T_SZ; ++t) {
        const bool hasNext = (t + 1 < T_SZ);

        // ===== phase A: h-MAC(t) (H)  ||  load x(t+1) (X) =====
        if (isH) {
            mac2<H_SZ>(hsbuf, w0_, w1_, hg + j0);
        } else if (hasNext) {
            const int i0 = tid - 128;
#pragma unroll
            for (int m = 0; m < 5; ++m) {
                const int idx = i0 + m * 128;
                if (m < 4 || idx < 520) {
                    const int p = idx / 65, k = idx - p * 65;
                    const float* xp = x + ((size_t)(b0 + 2 * p) * T_SZ + (t + 1)) * IN_SZ + k;
                    xsbuf[k * PST + p] = fpack(xp[0], xp[(size_t)T_SZ * IN_SZ]);
                }
            }
        }
        __syncthreads();

        // ===== phase B: update(t) (H)  ||  x-MAC(t+1) (X) =====
        if (isH) {
            const ull* xgc = xg + (t & 1) * (NP * G_SZ);
#pragma unroll
            for (int i = 0; i < 4; ++i) {
                const int p = pg * 4 + i;
                const ull* gx = xgc + p * G_SZ;
                const ull* gh = hg + p * G_SZ;
                ull sI = fadd2(gx[uu],       gh[uu]);
                ull sF = fadd2(gx[64 + uu],  gh[64 + uu]);
                ull sG = fadd2(gx[128 + uu], gh[128 + uu]);
                ull sO = fadd2(gx[192 + uu], gh[192 + uu]);
                float iL, iH, fL, fH, gL, gH, oL, oH;
                funpack(sI, iL, iH); funpack(sF, fL, fH);
                funpack(sG, gL, gH); funpack(sO, oL, oH);

                float iv = sigf(iL + bI);
                float fv = sigf(fL + bF);
                float gv = tanhf_(gL + bG);
                float ov = sigf(oL + bO);
                cL[i] = fv * cL[i] + iv * gv;
                float hLo = ov * tanhf_(cL[i]);

                iv = sigf(iH + bI);
                fv = sigf(fH + bF);
                gv = tanhf_(gH + bG);
                ov = sigf(oH + bO);
                cH[i] = fv * cH[i] + iv * gv;
                float hHi = ov * tanhf_(cH[i]);

                hsbuf[uu * PST + p] = fpack(hLo, hHi);
            }
        } else if (hasNext) {
            mac2<IN_SZ>(xsbuf, w0_, w1_, xg + ((t + 1) & 1) * (NP * G_SZ) + j0);
        }
        __syncthreads();
    }

    // ---- final FC head: out[b][o] = sigmoid(h . fcW[o] + fcb[o]) ----
    if (tid < BR * 7) {
        int r = tid / 7;
        int o = tid - r * 7;
        float s = fcb[o];
        const float* wrow = fcW + o * H_SZ;
#pragma unroll 8
        for (int u = 0; u < H_SZ; ++u) {
            float lo, hi;
            funpack(hsbuf[u * PST + (r >> 1)], lo, hi);
            s += wrow[u] * ((r & 1) ? hi : lo);
        }
        out[(size_t)(b0 + r) * 7 + o] = sigf(s);
    }
}

extern "C" void kernel_launch(void* const* d_in, const int* in_sizes, int n_in,
                              void* d_out, int out_size) {
    const float* x    = (const float*)d_in[0];
    const float* Wih  = (const float*)d_in[1];
    const float* Whh  = (const float*)d_in[2];
    const float* bih  = (const float*)d_in[3];
    const float* bhh  = (const float*)d_in[4];
    const float* fcW  = (const float*)d_in[5];
    const float* fcb  = (const float*)d_in[6];
    float* out = (float*)d_out;

    cudaFuncSetAttribute(lstm_fused_kernel,
                         cudaFuncAttributeMaxDynamicSharedMemorySize, SMEM_TOTAL);
    lstm_fused_kernel<<<B_SZ / BR, NTH, SMEM_TOTAL>>>(x, Wih, Whh, bih, bhh, fcW, fcb, out);
}

// round 9
// speedup vs baseline: 1.0946x; 1.0288x over previous
#include <cuda_runtime.h>
#include <cstdint>

#define B_SZ 2048
#define T_SZ 256
#define IN_SZ 65
#define H_SZ 64
#define G_SZ 256           // 4*H
#define BR 16              // batch rows per block
#define NP 8               // row pairs per block
#define PST 10             // ull stride per k-row (80B, keeps 16B alignment)
#define NTH 256

typedef unsigned long long ull;

__device__ __forceinline__ ull ffma2(ull a, ull b, ull c) {
    ull d;
    asm("fma.rn.f32x2 %0, %1, %2, %3;" : "=l"(d) : "l"(a), "l"(b), "l"(c));
    return d;
}
__device__ __forceinline__ ull fadd2(ull a, ull b) {
    ull d;
    asm("add.rn.f32x2 %0, %1, %2;" : "=l"(d) : "l"(a), "l"(b));
    return d;
}
__device__ __forceinline__ ull fdup(float v) {
    ull d;
    asm("mov.b64 %0, {%1, %1};" : "=l"(d) : "f"(v));
    return d;
}
__device__ __forceinline__ ull fpack(float lo, float hi) {
    ull d;
    asm("mov.b64 %0, {%1, %2};" : "=l"(d) : "f"(lo), "f"(hi));
    return d;
}
__device__ __forceinline__ void funpack(ull v, float& lo, float& hi) {
    asm("mov.b64 {%0, %1}, %2;" : "=f"(lo), "=f"(hi) : "l"(v));
}
__device__ __forceinline__ float ex2f(float x) {
    float y; asm("ex2.approx.f32 %0, %1;" : "=f"(y) : "f"(x)); return y;
}
__device__ __forceinline__ float rcpf(float x) {
    float y; asm("rcp.approx.f32 %0, %1;" : "=f"(y) : "f"(x)); return y;
}
__device__ __forceinline__ float sigf(float x) {
    return rcpf(1.0f + ex2f(-1.4426950408889634f * x));
}
__device__ __forceinline__ float tanhf_(float x) {
    return fmaf(2.0f, rcpf(1.0f + ex2f(-2.8853900817779268f * x)), -1.0f);
}

// dynamic smem layout (bytes)
#define XS_BYTES (IN_SZ * PST * 8)            // 5200   x row-pairs [65][PST]
#define HS_BYTES (H_SZ * PST * 8)             // 5120   h row-pairs [64][PST]
#define XG_BYTES (2 * NP * G_SZ * 8)          // 32768  x-part gates, ping-pong [2][8][256]
#define HG_BYTES (NP * G_SZ * 8)              // 16384  h-part gates [8][256]
#define SMEM_TOTAL (XS_BYTES + HS_BYTES + XG_BYTES + HG_BYTES)  // 59472

// MAC over N k-rows for TWO gate columns (j0, j0+128), FOUR row-pairs.
// Only 8 accumulators live -> ~80 regs of headroom for LDS pipelining.
template<int N>
__device__ __forceinline__ void mac2h(const ull* __restrict__ sp,
                                      const float* __restrict__ w0_,
                                      const float* __restrict__ w1_,
                                      ull* __restrict__ g /* gbuf + pbase*G_SZ + j0 */) {
    ull a0 = 0, a1 = 0, a2 = 0, a3 = 0;
    ull b0 = 0, b1 = 0, b2 = 0, b3 = 0;
#pragma unroll
    for (int k = 0; k < N; ++k) {
        const ull wd0 = fdup(w0_[k]);
        const ull wd1 = fdup(w1_[k]);
        ulonglong2 p01 = *(const ulonglong2*)(sp);
        ulonglong2 p23 = *(const ulonglong2*)(sp + 2);
        sp += PST;
        a0 = ffma2(wd0, p01.x, a0); a1 = ffma2(wd0, p01.y, a1);
        a2 = ffma2(wd0, p23.x, a2); a3 = ffma2(wd0, p23.y, a3);
        b0 = ffma2(wd1, p01.x, b0); b1 = ffma2(wd1, p01.y, b1);
        b2 = ffma2(wd1, p23.x, b2); b3 = ffma2(wd1, p23.y, b3);
    }
    g[0 * G_SZ] = a0; g[1 * G_SZ] = a1;
    g[2 * G_SZ] = a2; g[3 * G_SZ] = a3;
    ull* g2 = g + 128;
    g2[0 * G_SZ] = b0; g2[1 * G_SZ] = b1;
    g2[2 * G_SZ] = b2; g2[3 * G_SZ] = b3;
}

__global__ __launch_bounds__(NTH, 1)
void lstm_fused_kernel(const float* __restrict__ x,
                       const float* __restrict__ Wih,
                       const float* __restrict__ Whh,
                       const float* __restrict__ bih,
                       const float* __restrict__ bhh,
                       const float* __restrict__ fcW,
                       const float* __restrict__ fcb,
                       float* __restrict__ out) {
    extern __shared__ char sm_raw[];
    ull* xsbuf = (ull*)sm_raw;                                    // [65][PST]
    ull* hsbuf = (ull*)(sm_raw + XS_BYTES);                       // [64][PST]
    ull* xg    = (ull*)(sm_raw + XS_BYTES + HS_BYTES);            // [2][8][256]
    ull* hg    = (ull*)(sm_raw + XS_BYTES + HS_BYTES + XG_BYTES); // [8][256]

    const int tid = threadIdx.x;
    const int b0  = blockIdx.x * BR;
    const bool isH = tid < 128;        // warps 0-3: h-MAC + update; warps 4-7: x-engine
    const int j0 = tid & 127;          // owned gate columns j0 and j0+128

    // ---- weights -> registers (one-time) ----
    float w0_[IN_SZ], w1_[IN_SZ];
    if (isH) {
#pragma unroll
        for (int k = 0; k < H_SZ; ++k) {
            w0_[k] = Whh[j0 * H_SZ + k];
            w1_[k] = Whh[(j0 + 128) * H_SZ + k];
        }
        w0_[H_SZ] = 0.0f; w1_[H_SZ] = 0.0f;
    } else {
#pragma unroll
        for (int k = 0; k < IN_SZ; ++k) {
            w0_[k] = Wih[j0 * IN_SZ + k];
            w1_[k] = Wih[(j0 + 128) * IN_SZ + k];
        }
    }

    // ---- init: zero hsbuf, fill xsbuf with x(t=0) ----
    for (int i = tid; i < H_SZ * PST; i += NTH) hsbuf[i] = 0ULL;
    for (int idx = tid; idx < 520; idx += NTH) {
        const int p = idx / 65, k = idx - p * 65;
        const float* xp = x + (size_t)(b0 + 2 * p) * T_SZ * IN_SZ + k;
        xsbuf[k * PST + p] = fpack(xp[0], xp[(size_t)T_SZ * IN_SZ]);
    }

    // ---- update mapping (H threads): unit uu, row-pairs pg*4 .. pg*4+3 ----
    const int uu = tid & 63;           // 0..63
    const int pg = (tid >> 6) & 1;     // 0..1
    float bI = 0.f, bF = 0.f, bG = 0.f, bO = 0.f;
    if (isH) {
        bI = bih[uu]       + bhh[uu];
        bF = bih[64 + uu]  + bhh[64 + uu];
        bG = bih[128 + uu] + bhh[128 + uu];
        bO = bih[192 + uu] + bhh[192 + uu];
    }
    float cL[4] = {0.f, 0.f, 0.f, 0.f};
    float cH[4] = {0.f, 0.f, 0.f, 0.f};

    __syncthreads();

    // ---- prologue: x-MAC(0) -> xg[0] ----
    if (!isH) {
        mac2h<IN_SZ>(xsbuf, w0_, w1_, xg + j0);
        mac2h<IN_SZ>(xsbuf + 4, w0_, w1_, xg + 4 * G_SZ + j0);
    }
    __syncthreads();

    for (int t = 0; t < T_SZ; ++t) {
        const bool hasNext = (t + 1 < T_SZ);

        // ===== phase A: h-MAC(t) (H)  ||  load x(t+1) (X) =====
        if (isH) {
            mac2h<H_SZ>(hsbuf, w0_, w1_, hg + j0);
            mac2h<H_SZ>(hsbuf + 4, w0_, w1_, hg + 4 * G_SZ + j0);
        } else if (hasNext) {
            const int i0 = tid - 128;
#pragma unroll
            for (int m = 0; m < 5; ++m) {
                const int idx = i0 + m * 128;
                if (m < 4 || idx < 520) {
                    const int p = idx / 65, k = idx - p * 65;
                    const float* xp = x + ((size_t)(b0 + 2 * p) * T_SZ + (t + 1)) * IN_SZ + k;
                    xsbuf[k * PST + p] = fpack(xp[0], xp[(size_t)T_SZ * IN_SZ]);
                }
            }
        }
        __syncthreads();

        // ===== phase B: update(t) (H)  ||  x-MAC(t+1) (X) =====
        if (isH) {
            const ull* xgc = xg + (t & 1) * (NP * G_SZ);
#pragma unroll
            for (int i = 0; i < 4; ++i) {
                const int p = pg * 4 + i;
                const ull* gx = xgc + p * G_SZ;
                const ull* gh = hg + p * G_SZ;
                ull sI = fadd2(gx[uu],       gh[uu]);
                ull sF = fadd2(gx[64 + uu],  gh[64 + uu]);
                ull sG = fadd2(gx[128 + uu], gh[128 + uu]);
                ull sO = fadd2(gx[192 + uu], gh[192 + uu]);
                float iL, iH, fL, fH, gL, gH, oL, oH;
                funpack(sI, iL, iH); funpack(sF, fL, fH);
                funpack(sG, gL, gH); funpack(sO, oL, oH);

                float iv = sigf(iL + bI);
                float fv = sigf(fL + bF);
                float gv = tanhf_(gL + bG);
                float ov = sigf(oL + bO);
                cL[i] = fv * cL[i] + iv * gv;
                float hLo = ov * tanhf_(cL[i]);

                iv = sigf(iH + bI);
                fv = sigf(fH + bF);
                gv = tanhf_(gH + bG);
                ov = sigf(oH + bO);
                cH[i] = fv * cH[i] + iv * gv;
                float hHi = ov * tanhf_(cH[i]);

                hsbuf[uu * PST + p] = fpack(hLo, hHi);
            }
        } else if (hasNext) {
            ull* xgn = xg + ((t + 1) & 1) * (NP * G_SZ);
            mac2h<IN_SZ>(xsbuf, w0_, w1_, xgn + j0);
            mac2h<IN_SZ>(xsbuf + 4, w0_, w1_, xgn + 4 * G_SZ + j0);
        }
        __syncthreads();
    }

    // ---- final FC head: out[b][o] = sigmoid(h . fcW[o] + fcb[o]) ----
    if (tid < BR * 7) {
        int r = tid / 7;
        int o = tid - r * 7;
        float s = fcb[o];
        const float* wrow = fcW + o * H_SZ;
#pragma unroll 8
        for (int u = 0; u < H_SZ; ++u) {
            float lo, hi;
            funpack(hsbuf[u * PST + (r >> 1)], lo, hi);
            s += wrow[u] * ((r & 1) ? hi : lo);
        }
        out[(size_t)(b0 + r) * 7 + o] = sigf(s);
    }
}

extern "C" void kernel_launch(void* const* d_in, const int* in_sizes, int n_in,
                              void* d_out, int out_size) {
    const float* x    = (const float*)d_in[0];
    const float* Wih  = (const float*)d_in[1];
    const float* Whh  = (const float*)d_in[2];
    const float* bih  = (const float*)d_in[3];
    const float* bhh  = (const float*)d_in[4];
    const float* fcW  = (const float*)d_in[5];
    const float* fcb  = (const float*)d_in[6];
    float* out = (float*)d_out;

    cudaFuncSetAttribute(lstm_fused_kernel,
                         cudaFuncAttributeMaxDynamicSharedMemorySize, SMEM_TOTAL);
    lstm_fused_kernel<<<B_SZ / BR, NTH, SMEM_TOTAL>>>(x, Wih, Whh, bih, bhh, fcW, fcb, out);
}